// round 1
// baseline (speedup 1.0000x reference)
#include <cuda_runtime.h>
#include <math.h>

// ---------- problem constants (fixed by setup_inputs) ----------
#define BB    8
#define CC    192
#define HH    128
#define WWI   128
#define NTOK  (BB*HH*WWI)      // 131072 tokens
#define NHEAD 8
#define HD    24
#define WS    8
#define LW    (WS*WS)          // 64
#define NWIN  (BB*(HH/WS)*(WWI/WS)) // 2048
#define FFND  768
#define C3    (3*CC)           // 576
#define SCALE_ATT 0.20412414523193150818f  // 1/sqrt(24)

// ---------- scratch (static device globals; no allocation) ----------
__device__ __align__(256) float g_xt [NTOK*CC];    // residual stream, NHWC token-major
__device__ __align__(256) float g_xn [NTOK*CC];    // LN output
__device__ __align__(256) float g_qkv[NTOK*C3];    // qkv projections
__device__ __align__(256) float g_buf[NTOK*FFND];  // attn outs / FFN hidden
__device__ __align__(256) float g_gram[BB*NHEAD*HD*HD];
__device__ __align__(256) float g_attn[BB*NHEAD*HD*HD];

// ---------- helpers ----------
__device__ __forceinline__ float gelu_f(float x){
    return 0.5f * x * (1.f + erff(x * 0.70710678118654752440f));
}

// ---------- NCHW -> NHWC ----------
__global__ void nchw_to_nhwc(const float* __restrict__ x, float* __restrict__ xt){
    __shared__ float tile[32][33];
    int bh = blockIdx.z; int b = bh / HH; int h = bh % HH;
    int w0 = blockIdx.x*32, c0 = blockIdx.y*32;
    const float* xb = x + (size_t)b*CC*HH*WWI + (size_t)h*WWI;
    #pragma unroll
    for (int k=0;k<4;k++){
        int c = c0 + threadIdx.y + k*8;
        tile[threadIdx.y + k*8][threadIdx.x] = xb[(size_t)c*HH*WWI + w0 + threadIdx.x];
    }
    __syncthreads();
    size_t nbase = ((size_t)b*HH + h)*WWI;
    #pragma unroll
    for (int k=0;k<4;k++){
        int w = w0 + threadIdx.y + k*8;
        xt[(nbase + w)*CC + c0 + threadIdx.x] = tile[threadIdx.x][threadIdx.y + k*8];
    }
}

// ---------- NHWC -> NCHW ----------
__global__ void nhwc_to_nchw(const float* __restrict__ xt, float* __restrict__ y){
    __shared__ float tile[32][33];
    int bh = blockIdx.z; int b = bh / HH; int h = bh % HH;
    int w0 = blockIdx.x*32, c0 = blockIdx.y*32;
    size_t nbase = ((size_t)b*HH + h)*WWI;
    #pragma unroll
    for (int k=0;k<4;k++){
        int w = w0 + threadIdx.y + k*8;
        tile[threadIdx.y + k*8][threadIdx.x] = xt[(nbase + w)*CC + c0 + threadIdx.x];
    }
    __syncthreads();
    #pragma unroll
    for (int k=0;k<4;k++){
        int c = c0 + threadIdx.y + k*8;
        y[((size_t)(b*CC + c)*HH + h)*WWI + w0 + threadIdx.x] = tile[threadIdx.x][threadIdx.y + k*8];
    }
}

// ---------- LayerNorm over C=192: one warp per row ----------
__global__ void ln_kernel(const float* __restrict__ xin, const float* __restrict__ w,
                          const float* __restrict__ b, float* __restrict__ out){
    int warp = threadIdx.x >> 5, lane = threadIdx.x & 31;
    int row = blockIdx.x*4 + warp;
    const float* xr = xin + (size_t)row*CC;
    float v[6]; float s = 0.f, s2 = 0.f;
    #pragma unroll
    for (int i=0;i<6;i++){ v[i] = xr[lane + i*32]; s += v[i]; s2 += v[i]*v[i]; }
    #pragma unroll
    for (int o=16;o;o>>=1){ s += __shfl_xor_sync(~0u, s, o); s2 += __shfl_xor_sync(~0u, s2, o); }
    float m  = s * (1.f/CC);
    float var = s2*(1.f/CC) - m*m;
    float rs = rsqrtf(var + 1e-5f);
    float* orow = out + (size_t)row*CC;
    #pragma unroll
    for (int i=0;i<6;i++){ int c = lane + i*32; orow[c] = (v[i]-m)*rs*w[c] + b[c]; }
}

// ---------- generic GEMM: out[N,Of] = A[N,K] @ Wt[Of,K]^T (+bias)(+epilogue) ----------
// EPI 0: out = acc (+bias)     EPI 1: out = gelu(acc+bias)
// EPI 2: resid += gamma * (acc+bias)   (Of == CC)
template<int EPI>
__global__ __launch_bounds__(128) void gemm_kernel(
    const float* __restrict__ A, const float* __restrict__ Wt,
    const float* __restrict__ bias, float* __restrict__ out,
    const float* __restrict__ gamma, float* __restrict__ resid,
    int K, int Of)
{
    __shared__ __align__(16) float As[16][68];
    __shared__ __align__(16) float Bs[16][68];
    const int t  = threadIdx.x;
    const int m0 = blockIdx.y * 64;
    const int n0 = blockIdx.x * 64;
    const int ty = t >> 4;     // 0..7  -> 8 M rows
    const int tx = t & 15;     // 0..15 -> 4 N cols
    float acc[8][4];
    #pragma unroll
    for (int i=0;i<8;i++) { acc[i][0]=0;acc[i][1]=0;acc[i][2]=0;acc[i][3]=0; }

    const int r0  = t >> 2;       // 0..31
    const int kq0 = (t & 3) * 4;  // 0,4,8,12
    const float* Abase = A  + (size_t)(m0 + r0) * K + kq0;
    const float* Bbase = Wt + (size_t)(n0 + r0) * K + kq0;

    for (int k0 = 0; k0 < K; k0 += 16){
        float4 a0 = *(const float4*)(Abase + k0);
        float4 a1 = *(const float4*)(Abase + (size_t)32*K + k0);
        float4 b0 = *(const float4*)(Bbase + k0);
        float4 b1 = *(const float4*)(Bbase + (size_t)32*K + k0);
        __syncthreads();
        As[kq0+0][r0]   =a0.x; As[kq0+1][r0]   =a0.y; As[kq0+2][r0]   =a0.z; As[kq0+3][r0]   =a0.w;
        As[kq0+0][r0+32]=a1.x; As[kq0+1][r0+32]=a1.y; As[kq0+2][r0+32]=a1.z; As[kq0+3][r0+32]=a1.w;
        Bs[kq0+0][r0]   =b0.x; Bs[kq0+1][r0]   =b0.y; Bs[kq0+2][r0]   =b0.z; Bs[kq0+3][r0]   =b0.w;
        Bs[kq0+0][r0+32]=b1.x; Bs[kq0+1][r0+32]=b1.y; Bs[kq0+2][r0+32]=b1.z; Bs[kq0+3][r0+32]=b1.w;
        __syncthreads();
        #pragma unroll
        for (int k=0;k<16;k++){
            float4 av0 = *(const float4*)&As[k][ty*8];
            float4 av1 = *(const float4*)&As[k][ty*8+4];
            float4 bv  = *(const float4*)&Bs[k][tx*4];
            float am[8] = {av0.x,av0.y,av0.z,av0.w,av1.x,av1.y,av1.z,av1.w};
            float bn[4] = {bv.x,bv.y,bv.z,bv.w};
            #pragma unroll
            for (int mi=0;mi<8;mi++)
                #pragma unroll
                for (int ni=0;ni<4;ni++)
                    acc[mi][ni] = fmaf(am[mi], bn[ni], acc[mi][ni]);
        }
    }

    float4 bb = make_float4(0.f,0.f,0.f,0.f);
    if (bias) bb = *(const float4*)(bias + n0 + tx*4);
    float4 gg = make_float4(0.f,0.f,0.f,0.f);
    if (EPI == 2) gg = *(const float4*)(gamma + n0 + tx*4);

    #pragma unroll
    for (int mi=0; mi<8; mi++){
        int m = m0 + ty*8 + mi;
        float4 r;
        r.x = acc[mi][0] + bb.x; r.y = acc[mi][1] + bb.y;
        r.z = acc[mi][2] + bb.z; r.w = acc[mi][3] + bb.w;
        if (EPI == 1){
            r.x = gelu_f(r.x); r.y = gelu_f(r.y); r.z = gelu_f(r.z); r.w = gelu_f(r.w);
        }
        if (EPI == 2){
            float4* rp = (float4*)(resid + (size_t)m*CC + n0 + tx*4);
            float4 prev = *rp;
            prev.x += gg.x*r.x; prev.y += gg.y*r.y; prev.z += gg.z*r.z; prev.w += gg.w*r.w;
            *rp = prev;
        } else {
            *(float4*)(out + (size_t)m*Of + n0 + tx*4) = r;
        }
    }
}

// ---------- spatial window attention: one block per (window, head), 64 threads ----------
__global__ __launch_bounds__(64) void sa_attn_kernel(const float* __restrict__ qkv,
                                                     const float* __restrict__ btab,
                                                     float* __restrict__ out){
    __shared__ __align__(16) float qs[LW*HD];
    __shared__ __align__(16) float ks[LW*HD];
    __shared__ __align__(16) float vs[LW*HD];
    __shared__ float bt[225];
    int win = blockIdx.x, hh = blockIdx.y;
    int l = threadIdx.x;                      // query row / loaded token
    int b = win >> 8;                         // 256 windows per batch
    int wrem = win & 255;
    int wh = wrem >> 4, ww = wrem & 15;
    int i = l >> 3, j = l & 7;
    size_t n = ((size_t)(b*HH) + wh*WS + i)*WWI + ww*WS + j;

    const float4* qp = (const float4*)(qkv + n*C3 +        hh*HD);
    const float4* kp = (const float4*)(qkv + n*C3 + CC   + hh*HD);
    const float4* vp = (const float4*)(qkv + n*C3 + 2*CC + hh*HD);
    float4* qd = (float4*)&qs[l*HD];
    float4* kd = (float4*)&ks[l*HD];
    float4* vd = (float4*)&vs[l*HD];
    #pragma unroll
    for (int u=0;u<6;u++){ qd[u]=qp[u]; kd[u]=kp[u]; vd[u]=vp[u]; }
    for (int tt=l; tt<225; tt+=64) bt[tt] = btab[tt*NHEAD + hh];
    __syncthreads();

    float4 qf[6];
    #pragma unroll
    for (int u=0;u<6;u++) qf[u] = ((const float4*)&qs[l*HD])[u];

    float s[LW];
    #pragma unroll
    for (int m=0;m<LW;m++){
        const float4* kr = (const float4*)&ks[m*HD];
        float a = 0.f;
        #pragma unroll
        for (int u=0;u<6;u++){
            float4 kv = kr[u];
            a = fmaf(qf[u].x,kv.x, fmaf(qf[u].y,kv.y, fmaf(qf[u].z,kv.z, fmaf(qf[u].w,kv.w, a))));
        }
        int mi = m>>3, mj = m&7;
        s[m] = a*SCALE_ATT + bt[(i-mi+7)*15 + (j-mj+7)];
    }
    float mx = s[0];
    #pragma unroll
    for (int m=1;m<LW;m++) mx = fmaxf(mx, s[m]);
    float sum = 0.f;
    #pragma unroll
    for (int m=0;m<LW;m++){ s[m] = __expf(s[m]-mx); sum += s[m]; }
    float inv = 1.f/sum;

    float4 o[6];
    #pragma unroll
    for (int u=0;u<6;u++) o[u] = make_float4(0.f,0.f,0.f,0.f);
    #pragma unroll
    for (int m=0;m<LW;m++){
        float p = s[m];
        const float4* vr = (const float4*)&vs[m*HD];
        #pragma unroll
        for (int u=0;u<6;u++){
            float4 vv = vr[u];
            o[u].x = fmaf(p,vv.x,o[u].x); o[u].y = fmaf(p,vv.y,o[u].y);
            o[u].z = fmaf(p,vv.z,o[u].z); o[u].w = fmaf(p,vv.w,o[u].w);
        }
    }
    float4* op = (float4*)(out + n*CC + hh*HD);
    #pragma unroll
    for (int u=0;u<6;u++){
        o[u].x*=inv; o[u].y*=inv; o[u].z*=inv; o[u].w*=inv;
        op[u] = o[u];
    }
}

// ---------- channel attention: Gram matrices ----------
__global__ void zero_kernel(float* p, int n){
    int idx = blockIdx.x*blockDim.x + threadIdx.x;
    if (idx < n) p[idx] = 0.f;
}

__global__ __launch_bounds__(256) void ca_gram_kernel(const float* __restrict__ qkv,
                                                      float* __restrict__ gram){
    __shared__ __align__(16) float qs[256*HD];
    __shared__ __align__(16) float ks[256*HD];
    int bh = blockIdx.y; int b = bh >> 3; int hh = bh & 7;
    int chunk = blockIdx.x;  // 64 chunks of 256 tokens
    int t = threadIdx.x;
    size_t n = (size_t)b*(HH*WWI) + (size_t)chunk*256 + t;
    const float4* qp = (const float4*)(qkv + n*C3 +      hh*HD);
    const float4* kp = (const float4*)(qkv + n*C3 + CC + hh*HD);
    float4* qd = (float4*)&qs[t*HD];
    float4* kd = (float4*)&ks[t*HD];
    #pragma unroll
    for (int u=0;u<6;u++){ qd[u]=qp[u]; kd[u]=kp[u]; }
    __syncthreads();

    int p0 = t, p1 = t + 256, p2 = t + 512;
    int d0 = p0/HD, e0 = p0 - d0*HD;
    int d1 = p1/HD, e1 = p1 - d1*HD;
    int d2 = p2/HD, e2 = p2 - d2*HD;
    bool has2 = (p2 < NHEAD*HD*HD/8); // 576
    float a0=0.f, a1=0.f, a2=0.f;
    for (int l=0;l<256;l++){
        const float* qrow = &qs[l*HD];
        const float* krow = &ks[l*HD];
        a0 = fmaf(qrow[d0], krow[e0], a0);
        a1 = fmaf(qrow[d1], krow[e1], a1);
        if (has2) a2 = fmaf(qrow[d2], krow[e2], a2);
    }
    atomicAdd(&gram[bh*576 + p0], a0);
    atomicAdd(&gram[bh*576 + p1], a1);
    if (has2) atomicAdd(&gram[bh*576 + p2], a2);
}

__global__ void ca_softmax_kernel(const float* __restrict__ gram, float* __restrict__ attn){
    int bh = blockIdx.x; int d = threadIdx.x;
    if (d >= HD) return;
    const float* r = gram + bh*576 + d*HD;
    float v[HD];
    float mx = -1e30f;
    #pragma unroll
    for (int e=0;e<HD;e++){ v[e] = r[e]*SCALE_ATT; mx = fmaxf(mx, v[e]); }
    float sum = 0.f;
    #pragma unroll
    for (int e=0;e<HD;e++){ v[e] = __expf(v[e]-mx); sum += v[e]; }
    float inv = 1.f/sum;
    #pragma unroll
    for (int e=0;e<HD;e++) attn[bh*576 + d*HD + e] = v[e]*inv;
}

__global__ __launch_bounds__(192) void ca_apply_kernel(const float* __restrict__ qkv,
                                                       const float* __restrict__ attn,
                                                       float* __restrict__ out){
    __shared__ float at[NHEAD*HD*HD];   // 4608 floats
    __shared__ float vsm[CC];
    int t = threadIdx.x;
    size_t n0 = (size_t)blockIdx.x * 32;
    int b = (int)(n0 >> 14);            // 16384 tokens per batch
    for (int idx=t; idx<NHEAD*HD*HD; idx+=192) at[idx] = attn[(size_t)b*NHEAD*HD*HD + idx];
    __syncthreads();
    int hh = t / HD, d = t - hh*HD;
    float ar[HD];
    #pragma unroll
    for (int e=0;e<HD;e++) ar[e] = at[hh*576 + d*HD + e];
    for (int tok=0; tok<32; tok++){
        size_t n = n0 + tok;
        __syncthreads();
        vsm[t] = qkv[n*C3 + 2*CC + t];
        __syncthreads();
        float o = 0.f;
        #pragma unroll
        for (int e=0;e<HD;e++) o = fmaf(ar[e], vsm[hh*HD + e], o);
        out[n*CC + t] = o;
    }
}

// ---------- launch ----------
extern "C" void kernel_launch(void* const* d_in, const int* in_sizes, int n_in,
                              void* d_out, int out_size)
{
    const float* x           = (const float*)d_in[0];
    const float* sa_norm_w   = (const float*)d_in[1];
    const float* sa_norm_b   = (const float*)d_in[2];
    const float* sa_qkv_w    = (const float*)d_in[3];
    const float* sa_proj_w   = (const float*)d_in[4];
    const float* sa_proj_b   = (const float*)d_in[5];
    const float* sa_bias_tab = (const float*)d_in[6];
    const float* ca_norm_w   = (const float*)d_in[7];
    const float* ca_norm_b   = (const float*)d_in[8];
    const float* ca_qkv_w    = (const float*)d_in[9];
    const float* ca_proj_w   = (const float*)d_in[10];
    const float* ca_proj_b   = (const float*)d_in[11];
    const float* ffn_norm_w  = (const float*)d_in[12];
    const float* ffn_norm_b  = (const float*)d_in[13];
    const float* ffn_w1      = (const float*)d_in[14];
    const float* ffn_b1      = (const float*)d_in[15];
    const float* ffn_w2      = (const float*)d_in[16];
    const float* ffn_b2      = (const float*)d_in[17];
    const float* gamma1      = (const float*)d_in[18];
    const float* gamma2      = (const float*)d_in[19];
    const float* gamma3      = (const float*)d_in[20];
    float* y = (float*)d_out;

    float *xt, *xn, *qkv, *buf, *gram, *attn;
    cudaGetSymbolAddress((void**)&xt,   g_xt);
    cudaGetSymbolAddress((void**)&xn,   g_xn);
    cudaGetSymbolAddress((void**)&qkv,  g_qkv);
    cudaGetSymbolAddress((void**)&buf,  g_buf);
    cudaGetSymbolAddress((void**)&gram, g_gram);
    cudaGetSymbolAddress((void**)&attn, g_attn);

    dim3 tb(32,8);
    dim3 tg(WWI/32, CC/32, BB*HH);

    // residual stream in NHWC
    nchw_to_nhwc<<<tg, tb>>>(x, xt);

    // ---- spatial window attention ----
    ln_kernel<<<NTOK/4, 128>>>(xt, sa_norm_w, sa_norm_b, xn);
    gemm_kernel<0><<<dim3(C3/64, NTOK/64), 128>>>(xn, sa_qkv_w, nullptr, qkv, nullptr, nullptr, CC, C3);
    sa_attn_kernel<<<dim3(NWIN, NHEAD), 64>>>(qkv, sa_bias_tab, buf);
    gemm_kernel<2><<<dim3(CC/64, NTOK/64), 128>>>(buf, sa_proj_w, sa_proj_b, nullptr, gamma1, xt, CC, CC);

    // ---- channel attention ----
    ln_kernel<<<NTOK/4, 128>>>(xt, ca_norm_w, ca_norm_b, xn);
    gemm_kernel<0><<<dim3(C3/64, NTOK/64), 128>>>(xn, ca_qkv_w, nullptr, qkv, nullptr, nullptr, CC, C3);
    zero_kernel<<<(BB*NHEAD*HD*HD + 255)/256, 256>>>(gram, BB*NHEAD*HD*HD);
    ca_gram_kernel<<<dim3(64, BB*NHEAD), 256>>>(qkv, gram);
    ca_softmax_kernel<<<BB*NHEAD, 32>>>(gram, attn);
    ca_apply_kernel<<<NTOK/32, 192>>>(qkv, attn, buf);
    gemm_kernel<2><<<dim3(CC/64, NTOK/64), 128>>>(buf, ca_proj_w, ca_proj_b, nullptr, gamma2, xt, CC, CC);

    // ---- gated FFN ----
    ln_kernel<<<NTOK/4, 128>>>(xt, ffn_norm_w, ffn_norm_b, xn);
    gemm_kernel<1><<<dim3(FFND/64, NTOK/64), 128>>>(xn, ffn_w1, ffn_b1, buf, nullptr, nullptr, CC, FFND);
    gemm_kernel<2><<<dim3(CC/64, NTOK/64), 128>>>(buf, ffn_w2, ffn_b2, nullptr, gamma3, xt, FFND, CC);

    // back to NCHW
    nhwc_to_nchw<<<tg, tb>>>(xt, y);
}